// round 2
// baseline (speedup 1.0000x reference)
#include <cuda_runtime.h>
#include <cuda_bf16.h>
#include <math.h>

// Problem constants
#define S    2048
#define Hdim 4096
#define NH   32
#define HD   128
#define ROT  32
#define QKV3 12288            // 3*Hdim
#define HSTRIDE 384           // 3*HD per head inside qkv row

// Scratch (device globals; no allocation at runtime)
__device__ float g_qkv[(size_t)S * QKV3];            // 100 MB
__device__ float g_scores[(size_t)NH * S * S];       // 512 MB
__device__ float g_ctx[(size_t)S * Hdim];            // 33 MB

// ---------------------------------------------------------------------------
// Generic NT SGEMM: C[m,n] = sum_k A[m,k]*B[n,k] + bias[n]
// 128x128 tile, BK=8, 256 threads, 8x8 per thread.
// All dims assumed divisible by tile sizes (true here).
// ---------------------------------------------------------------------------
__global__ __launch_bounds__(256) void sgemm_nt(
    const float* __restrict__ A, const float* __restrict__ B,
    const float* __restrict__ bias, float* __restrict__ C,
    int K, int lda, int ldb, int ldc)
{
    __shared__ float As[8][128];
    __shared__ float Bs[8][128];

    const int tid  = threadIdx.x;
    const int lrow = tid >> 1;          // 0..127
    const int lk   = (tid & 1) * 4;     // 0 or 4
    const int tx   = tid & 15;          // 0..15 (col group)
    const int ty   = tid >> 4;          // 0..15 (row group)

    const float* Ab = A + (size_t)blockIdx.y * 128 * lda;
    const float* Bb = B + (size_t)blockIdx.x * 128 * ldb;

    float acc[8][8];
#pragma unroll
    for (int i = 0; i < 8; i++)
#pragma unroll
        for (int j = 0; j < 8; j++) acc[i][j] = 0.f;

    for (int k0 = 0; k0 < K; k0 += 8) {
        float4 a4 = *(const float4*)(Ab + (size_t)lrow * lda + k0 + lk);
        float4 b4 = *(const float4*)(Bb + (size_t)lrow * ldb + k0 + lk);
        As[lk + 0][lrow] = a4.x; As[lk + 1][lrow] = a4.y;
        As[lk + 2][lrow] = a4.z; As[lk + 3][lrow] = a4.w;
        Bs[lk + 0][lrow] = b4.x; Bs[lk + 1][lrow] = b4.y;
        Bs[lk + 2][lrow] = b4.z; Bs[lk + 3][lrow] = b4.w;
        __syncthreads();

#pragma unroll
        for (int kk = 0; kk < 8; kk++) {
            float ar[8], br[8];
#pragma unroll
            for (int i = 0; i < 8; i++) ar[i] = As[kk][ty * 8 + i];
#pragma unroll
            for (int j = 0; j < 8; j++) br[j] = Bs[kk][tx * 8 + j];
#pragma unroll
            for (int i = 0; i < 8; i++)
#pragma unroll
                for (int j = 0; j < 8; j++) acc[i][j] += ar[i] * br[j];
        }
        __syncthreads();
    }

#pragma unroll
    for (int i = 0; i < 8; i++) {
        int row = blockIdx.y * 128 + ty * 8 + i;
#pragma unroll
        for (int j = 0; j < 8; j++) {
            int col = blockIdx.x * 128 + tx * 8 + j;
            C[(size_t)row * ldc + col] = acc[i][j] + bias[col];
        }
    }
}

// ---------------------------------------------------------------------------
// In-place partial RoPE on q,k slices of g_qkv.
// One thread per (s, h, pair i in [0,16), which in {q,k}).
// ---------------------------------------------------------------------------
__global__ void rope_kernel(float* __restrict__ qkv)
{
    int idx = blockIdx.x * blockDim.x + threadIdx.x;
    const int total = S * NH * 16 * 2;
    if (idx >= total) return;

    int i = idx & 15;            // pair index 0..15
    int r = idx >> 4;
    int h = r & 31;
    r >>= 5;
    int which = r & 1;           // 0 = q, 1 = k
    int s = r >> 1;

    float inv  = powf(10000.0f, -(float)i / 16.0f);   // BASE^(-2i/ROT)
    float ang  = (float)s * inv;
    float c, sn;
    sincosf(ang, &sn, &c);

    float* base = qkv + (size_t)s * QKV3 + h * HSTRIDE + which * HD;
    float x1 = base[i];
    float x2 = base[i + 16];
    base[i]      = x1 * c - x2 * sn;
    base[i + 16] = x2 * c + x1 * sn;
}

// ---------------------------------------------------------------------------
// Scores: scores[h][i][j] = (j<=i) ? q_i·k_j / sqrt(HD) : -10000
// 128x128 tile per block, K=HD=128. Fully-masked tiles fast-filled.
// ---------------------------------------------------------------------------
__global__ __launch_bounds__(256) void scores_kernel(
    const float* __restrict__ qkv, float* __restrict__ scores)
{
    const int h  = blockIdx.z;
    const int bi = blockIdx.y;   // query tile
    const int bj = blockIdx.x;   // key tile
    float* out = scores + (size_t)h * S * S;

    if (bj > bi) {               // fully above diagonal
        for (int e = threadIdx.x; e < 128 * 128; e += 256) {
            int i = e >> 7, j = e & 127;
            out[(size_t)(bi * 128 + i) * S + bj * 128 + j] = -10000.0f;
        }
        return;
    }

    const float* Qb = qkv + (size_t)bi * 128 * QKV3 + h * HSTRIDE;        // q
    const float* Kb = qkv + (size_t)bj * 128 * QKV3 + h * HSTRIDE + HD;   // k

    __shared__ float As[8][128];
    __shared__ float Bs[8][128];

    const int tid  = threadIdx.x;
    const int lrow = tid >> 1;
    const int lk   = (tid & 1) * 4;
    const int tx   = tid & 15;
    const int ty   = tid >> 4;

    float acc[8][8];
#pragma unroll
    for (int i = 0; i < 8; i++)
#pragma unroll
        for (int j = 0; j < 8; j++) acc[i][j] = 0.f;

    for (int k0 = 0; k0 < HD; k0 += 8) {
        float4 a4 = *(const float4*)(Qb + (size_t)lrow * QKV3 + k0 + lk);
        float4 b4 = *(const float4*)(Kb + (size_t)lrow * QKV3 + k0 + lk);
        As[lk + 0][lrow] = a4.x; As[lk + 1][lrow] = a4.y;
        As[lk + 2][lrow] = a4.z; As[lk + 3][lrow] = a4.w;
        Bs[lk + 0][lrow] = b4.x; Bs[lk + 1][lrow] = b4.y;
        Bs[lk + 2][lrow] = b4.z; Bs[lk + 3][lrow] = b4.w;
        __syncthreads();

#pragma unroll
        for (int kk = 0; kk < 8; kk++) {
            float ar[8], br[8];
#pragma unroll
            for (int i = 0; i < 8; i++) ar[i] = As[kk][ty * 8 + i];
#pragma unroll
            for (int j = 0; j < 8; j++) br[j] = Bs[kk][tx * 8 + j];
#pragma unroll
            for (int i = 0; i < 8; i++)
#pragma unroll
                for (int j = 0; j < 8; j++) acc[i][j] += ar[i] * br[j];
        }
        __syncthreads();
    }

    const float scale = 0.08838834764831845f;   // 1/sqrt(128)
#pragma unroll
    for (int i = 0; i < 8; i++) {
        int gi = bi * 128 + ty * 8 + i;
#pragma unroll
        for (int j = 0; j < 8; j++) {
            int gj = bj * 128 + tx * 8 + j;
            float v = (gj <= gi) ? acc[i][j] * scale : -10000.0f;
            out[(size_t)gi * S + gj] = v;
        }
    }
}

// ---------------------------------------------------------------------------
// Row softmax over S=2048 elements. One block per (row, head), 256 threads,
// 8 contiguous elements per thread kept in registers.
// ---------------------------------------------------------------------------
__global__ __launch_bounds__(256) void softmax_kernel(float* __restrict__ sc)
{
    float* p = sc + ((size_t)blockIdx.y * S + blockIdx.x) * S;
    const int tid = threadIdx.x;

    float4 v0 = ((const float4*)p)[tid * 2];
    float4 v1 = ((const float4*)p)[tid * 2 + 1];
    float e[8] = { v0.x, v0.y, v0.z, v0.w, v1.x, v1.y, v1.z, v1.w };

    __shared__ float red[256];
    float m = e[0];
#pragma unroll
    for (int i = 1; i < 8; i++) m = fmaxf(m, e[i]);
    red[tid] = m;
    __syncthreads();
    for (int s2 = 128; s2 > 0; s2 >>= 1) {
        if (tid < s2) red[tid] = fmaxf(red[tid], red[tid + s2]);
        __syncthreads();
    }
    m = red[0];
    __syncthreads();

    float sum = 0.f;
#pragma unroll
    for (int i = 0; i < 8; i++) { e[i] = expf(e[i] - m); sum += e[i]; }
    red[tid] = sum;
    __syncthreads();
    for (int s2 = 128; s2 > 0; s2 >>= 1) {
        if (tid < s2) red[tid] += red[tid + s2];
        __syncthreads();
    }
    float inv = 1.0f / red[0];

    float4 o0 = { e[0] * inv, e[1] * inv, e[2] * inv, e[3] * inv };
    float4 o1 = { e[4] * inv, e[5] * inv, e[6] * inv, e[7] * inv };
    ((float4*)p)[tid * 2]     = o0;
    ((float4*)p)[tid * 2 + 1] = o1;
}

// ---------------------------------------------------------------------------
// ctx[s, h*128+d] = sum_t P[h][s][t] * v[t, h, d]
// Block: 64 query rows x full 128 head dim, one head. BK=16.
// Causal: K loop truncated at end of the query tile.
// ---------------------------------------------------------------------------
__global__ __launch_bounds__(256) void pv_kernel(
    const float* __restrict__ P_all, const float* __restrict__ qkv,
    float* __restrict__ ctx)
{
    const int h    = blockIdx.y;
    const int brow = blockIdx.x;
    const float* P = P_all + (size_t)h * S * S;
    const float* V = qkv + h * HSTRIDE + 2 * HD;

    __shared__ float Ps[64][16];
    __shared__ float Vs[16][128];

    const int tid = threadIdx.x;
    const int ty  = tid >> 5;        // 0..7 -> 8 rows each
    const int tx  = tid & 31;        // 0..31 -> 4 cols each

    float acc[8][4];
#pragma unroll
    for (int i = 0; i < 8; i++)
#pragma unroll
        for (int j = 0; j < 4; j++) acc[i][j] = 0.f;

    const int kmax = brow * 64 + 64;     // causal truncation
    const int pr = tid >> 2, pk = (tid & 3) * 4;
    const int vt = tid >> 4, vd = (tid & 15) * 8;

    for (int k0 = 0; k0 < kmax; k0 += 16) {
        float4 p4 = *(const float4*)(P + (size_t)(brow * 64 + pr) * S + k0 + pk);
        *(float4*)&Ps[pr][pk] = p4;
        const float* vrow = V + (size_t)(k0 + vt) * QKV3;
        *(float4*)&Vs[vt][vd]     = *(const float4*)(vrow + vd);
        *(float4*)&Vs[vt][vd + 4] = *(const float4*)(vrow + vd + 4);
        __syncthreads();

#pragma unroll
        for (int kk = 0; kk < 16; kk++) {
            float b0 = Vs[kk][tx * 4 + 0];
            float b1 = Vs[kk][tx * 4 + 1];
            float b2 = Vs[kk][tx * 4 + 2];
            float b3 = Vs[kk][tx * 4 + 3];
#pragma unroll
            for (int i = 0; i < 8; i++) {
                float a = Ps[ty * 8 + i][kk];
                acc[i][0] += a * b0;
                acc[i][1] += a * b1;
                acc[i][2] += a * b2;
                acc[i][3] += a * b3;
            }
        }
        __syncthreads();
    }

#pragma unroll
    for (int i = 0; i < 8; i++) {
        int row = brow * 64 + ty * 8 + i;
#pragma unroll
        for (int j = 0; j < 4; j++) {
            int col = h * HD + tx * 4 + j;
            ctx[(size_t)row * Hdim + col] = acc[i][j];
        }
    }
}

// ---------------------------------------------------------------------------
// Launch
// ---------------------------------------------------------------------------
extern "C" void kernel_launch(void* const* d_in, const int* in_sizes, int n_in,
                              void* d_out, int out_size)
{
    const float* hidden  = (const float*)d_in[0];
    // d_in[1] = attention_mask (causal; unused — structure known)
    const float* W_qkv   = (const float*)d_in[2];
    const float* b_qkv   = (const float*)d_in[3];
    const float* W_dense = (const float*)d_in[4];
    const float* b_dense = (const float*)d_in[5];
    float* out = (float*)d_out;

    float *qkv, *scores, *ctx;
    cudaGetSymbolAddress((void**)&qkv,    g_qkv);
    cudaGetSymbolAddress((void**)&scores, g_scores);
    cudaGetSymbolAddress((void**)&ctx,    g_ctx);

    // 1) QKV GEMM: [2048,4096] x [12288,4096]^T -> [2048,12288]
    {
        dim3 grid(QKV3 / 128, S / 128);
        sgemm_nt<<<grid, 256>>>(hidden, W_qkv, b_qkv, qkv,
                                Hdim, Hdim, Hdim, QKV3);
    }

    // 2) RoPE in place on q,k
    {
        int total = S * NH * 16 * 2;
        rope_kernel<<<(total + 255) / 256, 256>>>(qkv);
    }

    // 3) Scores with causal mask + scale
    {
        dim3 grid(S / 128, S / 128, NH);
        scores_kernel<<<grid, 256>>>(qkv, scores);
    }

    // 4) Row softmax
    {
        dim3 grid(S, NH);
        softmax_kernel<<<grid, 256>>>(scores);
    }

    // 5) P @ V -> ctx [2048, 4096]
    {
        dim3 grid(S / 64, NH);
        pv_kernel<<<grid, 256>>>(scores, qkv, ctx);
    }

    // 6) Dense GEMM: ctx [2048,4096] x W_dense^T -> out
    {
        dim3 grid(Hdim / 128, S / 128);
        sgemm_nt<<<grid, 256>>>(ctx, W_dense, b_dense, out,
                                Hdim, Hdim, Hdim, Hdim);
    }
}

// round 4
// speedup vs baseline: 2.8174x; 2.8174x over previous
#include <cuda_runtime.h>
#include <math.h>

// Problem constants
#define S    2048
#define Hdim 4096
#define NH   32
#define HD   128
#define QKV3 12288            // 3*Hdim
#define HSTRIDE 384           // 3*HD per head inside a qkv row

// Scratch (device globals; no runtime allocation)
__device__ float g_qkv[(size_t)S * QKV3];            // 100 MB
__device__ float g_scores[(size_t)NH * S * S];       // 512 MB
__device__ float g_ctx[(size_t)S * Hdim];            // 33 MB

// ---------------------------------------------------------------------------
// tf32 helpers
// ---------------------------------------------------------------------------
__device__ __forceinline__ float to_tf32(float x) {
    unsigned r;
    asm("cvt.rna.tf32.f32 %0, %1;" : "=r"(r) : "f"(x));
    return __uint_as_float(r);
}

__device__ __forceinline__ void mma8(float c[4], const float4& a, const float2& b) {
    asm volatile(
        "mma.sync.aligned.m16n8k8.row.col.f32.tf32.tf32.f32 "
        "{%0,%1,%2,%3},{%4,%5,%6,%7},{%8,%9},{%0,%1,%2,%3};\n"
        : "+f"(c[0]), "+f"(c[1]), "+f"(c[2]), "+f"(c[3])
        : "r"(__float_as_uint(a.x)), "r"(__float_as_uint(a.y)),
          "r"(__float_as_uint(a.z)), "r"(__float_as_uint(a.w)),
          "r"(__float_as_uint(b.x)), "r"(__float_as_uint(b.y)));
}

// Shared-tile layouts (per 128x128 block, BK=32):
//  As4[kb][p][c] : float4 = (A[m1][k], A[m1+8][k], A[m1][k+4], A[m1+8][k+4])
//                  k = kb*8+c, p = g*8+r8, m1 = g*16+r8
//  Bs2[kb][n][c] : float2 = (B[n][k], B[n][k+4]), k = kb*8+c
// Fragment loads are warp-contiguous (512B / 256B) -> conflict-free.

// ---------------------------------------------------------------------------
// Generic NT GEMM: C[m,n] = sum_k A[m,k]*B[n,k] + bias[n]
// ---------------------------------------------------------------------------
__global__ __launch_bounds__(256) void gemm_tc_nt(
    const float* __restrict__ A, const float* __restrict__ B,
    const float* __restrict__ bias, float* __restrict__ C,
    int K, int lda, int ldb, int ldc)
{
    __shared__ float4 As4[4][64][4];   // 16 KB
    __shared__ float2 Bs2[4][128][4];  // 16 KB

    const int tid = threadIdx.x, lane = tid & 31, wid = tid >> 5;
    const int warp_m = wid & 1, warp_n = wid >> 1;   // 2 x 4 warps
    const int t4 = lane >> 2, c4 = lane & 3;

    // Loader assignment
    const int kbA = tid & 3, pA = tid >> 2;          // 4 x 64
    const int m1  = ((pA >> 3) << 4) + (pA & 7);
    const int kbB = tid & 3, nB = tid >> 2;          // 4 x 64 (x2 passes)

    const float* a1p = A + (size_t)(blockIdx.y * 128 + m1) * lda + kbA * 8;
    const float* a2p = a1p + (size_t)8 * lda;
    const float* b1p = B + (size_t)(blockIdx.x * 128 + nB) * ldb + kbB * 8;
    const float* b2p = b1p + (size_t)64 * ldb;

    float acc[4][4][4];
#pragma unroll
    for (int i = 0; i < 4; i++)
#pragma unroll
        for (int j = 0; j < 4; j++)
#pragma unroll
            for (int r = 0; r < 4; r++) acc[i][j][r] = 0.f;

    float4 xa0, xa1, ya0, ya1, u0, u1, v0, v1;
    // prefetch chunk 0
    xa0 = *(const float4*)(a1p);     xa1 = *(const float4*)(a1p + 4);
    ya0 = *(const float4*)(a2p);     ya1 = *(const float4*)(a2p + 4);
    u0  = *(const float4*)(b1p);     u1  = *(const float4*)(b1p + 4);
    v0  = *(const float4*)(b2p);     v1  = *(const float4*)(b2p + 4);

    for (int k0 = 0; k0 < K; k0 += 32) {
        __syncthreads();
        As4[kbA][pA][0] = make_float4(to_tf32(xa0.x), to_tf32(ya0.x), to_tf32(xa1.x), to_tf32(ya1.x));
        As4[kbA][pA][1] = make_float4(to_tf32(xa0.y), to_tf32(ya0.y), to_tf32(xa1.y), to_tf32(ya1.y));
        As4[kbA][pA][2] = make_float4(to_tf32(xa0.z), to_tf32(ya0.z), to_tf32(xa1.z), to_tf32(ya1.z));
        As4[kbA][pA][3] = make_float4(to_tf32(xa0.w), to_tf32(ya0.w), to_tf32(xa1.w), to_tf32(ya1.w));
        Bs2[kbB][nB][0]      = make_float2(to_tf32(u0.x), to_tf32(u1.x));
        Bs2[kbB][nB][1]      = make_float2(to_tf32(u0.y), to_tf32(u1.y));
        Bs2[kbB][nB][2]      = make_float2(to_tf32(u0.z), to_tf32(u1.z));
        Bs2[kbB][nB][3]      = make_float2(to_tf32(u0.w), to_tf32(u1.w));
        Bs2[kbB][nB + 64][0] = make_float2(to_tf32(v0.x), to_tf32(v1.x));
        Bs2[kbB][nB + 64][1] = make_float2(to_tf32(v0.y), to_tf32(v1.y));
        Bs2[kbB][nB + 64][2] = make_float2(to_tf32(v0.z), to_tf32(v1.z));
        Bs2[kbB][nB + 64][3] = make_float2(to_tf32(v0.w), to_tf32(v1.w));
        __syncthreads();

        int kn = k0 + 32;
        if (kn < K) {   // prefetch next chunk (overlaps with MMA below)
            xa0 = *(const float4*)(a1p + kn);     xa1 = *(const float4*)(a1p + kn + 4);
            ya0 = *(const float4*)(a2p + kn);     ya1 = *(const float4*)(a2p + kn + 4);
            u0  = *(const float4*)(b1p + kn);     u1  = *(const float4*)(b1p + kn + 4);
            v0  = *(const float4*)(b2p + kn);     v1  = *(const float4*)(b2p + kn + 4);
        }

#pragma unroll
        for (int kb = 0; kb < 4; kb++) {
            float4 af[4]; float2 bf[4];
#pragma unroll
            for (int mt = 0; mt < 4; mt++)
                af[mt] = As4[kb][((warp_m * 4 + mt) << 3) + t4][c4];
#pragma unroll
            for (int nt = 0; nt < 4; nt++)
                bf[nt] = Bs2[kb][warp_n * 32 + nt * 8 + t4][c4];
#pragma unroll
            for (int mt = 0; mt < 4; mt++)
#pragma unroll
                for (int nt = 0; nt < 4; nt++) mma8(acc[mt][nt], af[mt], bf[nt]);
        }
    }

#pragma unroll
    for (int mt = 0; mt < 4; mt++) {
        int r0 = blockIdx.y * 128 + warp_m * 64 + mt * 16 + t4;
#pragma unroll
        for (int nt = 0; nt < 4; nt++) {
            int cc = blockIdx.x * 128 + warp_n * 32 + nt * 8 + 2 * c4;
            float b0 = bias[cc], b1 = bias[cc + 1];
            *(float2*)&C[(size_t)r0 * ldc + cc] =
                make_float2(acc[mt][nt][0] + b0, acc[mt][nt][1] + b1);
            *(float2*)&C[(size_t)(r0 + 8) * ldc + cc] =
                make_float2(acc[mt][nt][2] + b0, acc[mt][nt][3] + b1);
        }
    }
}

// ---------------------------------------------------------------------------
// RoPE (in place on q,k slices of g_qkv)
// ---------------------------------------------------------------------------
__global__ void rope_kernel(float* __restrict__ qkv)
{
    int idx = blockIdx.x * blockDim.x + threadIdx.x;
    const int total = S * NH * 16 * 2;
    if (idx >= total) return;

    int i = idx & 15;
    int r = idx >> 4;
    int h = r & 31;
    r >>= 5;
    int which = r & 1;
    int s = r >> 1;

    float inv = powf(10000.0f, -(float)i / 16.0f);
    float ang = (float)s * inv;
    float c, sn;
    sincosf(ang, &sn, &c);

    float* base = qkv + (size_t)s * QKV3 + h * HSTRIDE + which * HD;
    float x1 = base[i];
    float x2 = base[i + 16];
    base[i]      = x1 * c - x2 * sn;
    base[i + 16] = x2 * c + x1 * sn;
}

// ---------------------------------------------------------------------------
// Scores (tensor core): scores[h][i][j] = (j<=i) ? q_i.k_j/sqrt(HD) : -1e4
// ---------------------------------------------------------------------------
__global__ __launch_bounds__(256) void scores_tc(
    const float* __restrict__ qkv, float* __restrict__ scores)
{
    const int h  = blockIdx.z;
    const int bi = blockIdx.y;
    const int bj = blockIdx.x;
    float* out = scores + (size_t)h * S * S;

    if (bj > bi) {
        for (int e = threadIdx.x; e < 128 * 128; e += 256) {
            int i = e >> 7, j = e & 127;
            out[(size_t)(bi * 128 + i) * S + bj * 128 + j] = -10000.0f;
        }
        return;
    }

    __shared__ float4 As4[4][64][4];
    __shared__ float2 Bs2[4][128][4];

    const int tid = threadIdx.x, lane = tid & 31, wid = tid >> 5;
    const int warp_m = wid & 1, warp_n = wid >> 1;
    const int t4 = lane >> 2, c4 = lane & 3;

    const int kbA = tid & 3, pA = tid >> 2;
    const int m1  = ((pA >> 3) << 4) + (pA & 7);
    const int kbB = tid & 3, nB = tid >> 2;

    const float* a1p = qkv + (size_t)(bi * 128 + m1) * QKV3 + h * HSTRIDE + kbA * 8;
    const float* a2p = a1p + (size_t)8 * QKV3;
    const float* b1p = qkv + (size_t)(bj * 128 + nB) * QKV3 + h * HSTRIDE + HD + kbB * 8;
    const float* b2p = b1p + (size_t)64 * QKV3;

    float acc[4][4][4];
#pragma unroll
    for (int i = 0; i < 4; i++)
#pragma unroll
        for (int j = 0; j < 4; j++)
#pragma unroll
            for (int r = 0; r < 4; r++) acc[i][j][r] = 0.f;

    float4 xa0, xa1, ya0, ya1, u0, u1, v0, v1;
    xa0 = *(const float4*)(a1p);  xa1 = *(const float4*)(a1p + 4);
    ya0 = *(const float4*)(a2p);  ya1 = *(const float4*)(a2p + 4);
    u0  = *(const float4*)(b1p);  u1  = *(const float4*)(b1p + 4);
    v0  = *(const float4*)(b2p);  v1  = *(const float4*)(b2p + 4);

    for (int k0 = 0; k0 < HD; k0 += 32) {
        __syncthreads();
        As4[kbA][pA][0] = make_float4(to_tf32(xa0.x), to_tf32(ya0.x), to_tf32(xa1.x), to_tf32(ya1.x));
        As4[kbA][pA][1] = make_float4(to_tf32(xa0.y), to_tf32(ya0.y), to_tf32(xa1.y), to_tf32(ya1.y));
        As4[kbA][pA][2] = make_float4(to_tf32(xa0.z), to_tf32(ya0.z), to_tf32(xa1.z), to_tf32(ya1.z));
        As4[kbA][pA][3] = make_float4(to_tf32(xa0.w), to_tf32(ya0.w), to_tf32(xa1.w), to_tf32(ya1.w));
        Bs2[kbB][nB][0]      = make_float2(to_tf32(u0.x), to_tf32(u1.x));
        Bs2[kbB][nB][1]      = make_float2(to_tf32(u0.y), to_tf32(u1.y));
        Bs2[kbB][nB][2]      = make_float2(to_tf32(u0.z), to_tf32(u1.z));
        Bs2[kbB][nB][3]      = make_float2(to_tf32(u0.w), to_tf32(u1.w));
        Bs2[kbB][nB + 64][0] = make_float2(to_tf32(v0.x), to_tf32(v1.x));
        Bs2[kbB][nB + 64][1] = make_float2(to_tf32(v0.y), to_tf32(v1.y));
        Bs2[kbB][nB + 64][2] = make_float2(to_tf32(v0.z), to_tf32(v1.z));
        Bs2[kbB][nB + 64][3] = make_float2(to_tf32(v0.w), to_tf32(v1.w));
        __syncthreads();

        int kn = k0 + 32;
        if (kn < HD) {
            xa0 = *(const float4*)(a1p + kn);  xa1 = *(const float4*)(a1p + kn + 4);
            ya0 = *(const float4*)(a2p + kn);  ya1 = *(const float4*)(a2p + kn + 4);
            u0  = *(const float4*)(b1p + kn);  u1  = *(const float4*)(b1p + kn + 4);
            v0  = *(const float4*)(b2p + kn);  v1  = *(const float4*)(b2p + kn + 4);
        }

#pragma unroll
        for (int kb = 0; kb < 4; kb++) {
            float4 af[4]; float2 bf[4];
#pragma unroll
            for (int mt = 0; mt < 4; mt++)
                af[mt] = As4[kb][((warp_m * 4 + mt) << 3) + t4][c4];
#pragma unroll
            for (int nt = 0; nt < 4; nt++)
                bf[nt] = Bs2[kb][warp_n * 32 + nt * 8 + t4][c4];
#pragma unroll
            for (int mt = 0; mt < 4; mt++)
#pragma unroll
                for (int nt = 0; nt < 4; nt++) mma8(acc[mt][nt], af[mt], bf[nt]);
        }
    }

    const float scale = 0.08838834764831845f;   // 1/sqrt(128)
#pragma unroll
    for (int mt = 0; mt < 4; mt++) {
        int r0 = bi * 128 + warp_m * 64 + mt * 16 + t4;
#pragma unroll
        for (int nt = 0; nt < 4; nt++) {
            int cc = bj * 128 + warp_n * 32 + nt * 8 + 2 * c4;
            float s00 = (cc     <= r0    ) ? acc[mt][nt][0] * scale : -10000.0f;
            float s01 = (cc + 1 <= r0    ) ? acc[mt][nt][1] * scale : -10000.0f;
            float s10 = (cc     <= r0 + 8) ? acc[mt][nt][2] * scale : -10000.0f;
            float s11 = (cc + 1 <= r0 + 8) ? acc[mt][nt][3] * scale : -10000.0f;
            *(float2*)&out[(size_t)r0 * S + cc]       = make_float2(s00, s01);
            *(float2*)&out[(size_t)(r0 + 8) * S + cc] = make_float2(s10, s11);
        }
    }
}

// ---------------------------------------------------------------------------
// Row softmax over S=2048 elements
// ---------------------------------------------------------------------------
__global__ __launch_bounds__(256) void softmax_kernel(float* __restrict__ sc)
{
    float* p = sc + ((size_t)blockIdx.y * S + blockIdx.x) * S;
    const int tid = threadIdx.x;

    float4 v0 = ((const float4*)p)[tid * 2];
    float4 v1 = ((const float4*)p)[tid * 2 + 1];
    float e[8] = { v0.x, v0.y, v0.z, v0.w, v1.x, v1.y, v1.z, v1.w };

    __shared__ float red[256];
    float m = e[0];
#pragma unroll
    for (int i = 1; i < 8; i++) m = fmaxf(m, e[i]);
    red[tid] = m;
    __syncthreads();
    for (int s2 = 128; s2 > 0; s2 >>= 1) {
        if (tid < s2) red[tid] = fmaxf(red[tid], red[tid + s2]);
        __syncthreads();
    }
    m = red[0];
    __syncthreads();

    float sum = 0.f;
#pragma unroll
    for (int i = 0; i < 8; i++) { e[i] = expf(e[i] - m); sum += e[i]; }
    red[tid] = sum;
    __syncthreads();
    for (int s2 = 128; s2 > 0; s2 >>= 1) {
        if (tid < s2) red[tid] += red[tid + s2];
        __syncthreads();
    }
    float inv = 1.0f / red[0];

    float4 o0 = { e[0] * inv, e[1] * inv, e[2] * inv, e[3] * inv };
    float4 o1 = { e[4] * inv, e[5] * inv, e[6] * inv, e[7] * inv };
    ((float4*)p)[tid * 2]     = o0;
    ((float4*)p)[tid * 2 + 1] = o1;
}

// ---------------------------------------------------------------------------
// P @ V (tensor core): ctx[s, h*128+d] = sum_t P[h][s][t] * v[t,h,d]
// Block tile: 128 s-rows x 128 d.  K = (bi+1)*128 (causal truncation).
// ---------------------------------------------------------------------------
__global__ __launch_bounds__(256) void pv_tc(
    const float* __restrict__ P_all, const float* __restrict__ qkv,
    float* __restrict__ ctx)
{
    const int bi = blockIdx.x;
    const int h  = blockIdx.y;
    const float* P = P_all + (size_t)h * S * S + (size_t)bi * 128 * S;
    const float* V = qkv + h * HSTRIDE + 2 * HD;

    __shared__ float4 As4[4][64][4];
    __shared__ float2 Bs2[4][128][4];

    const int tid = threadIdx.x, lane = tid & 31, wid = tid >> 5;
    const int warp_m = wid & 1, warp_n = wid >> 1;
    const int t4 = lane >> 2, c4 = lane & 3;

    const int kbA = tid & 3, pA = tid >> 2;
    const int m1  = ((pA >> 3) << 4) + (pA & 7);
    const int nV  = tid & 127;          // V column (d)
    const int kbV0 = (tid >> 7) * 2;    // this thread covers kb = kbV0, kbV0+1

    const float* a1p = P + (size_t)m1 * S + kbA * 8;
    const float* a2p = a1p + (size_t)8 * S;
    const float* vp  = V + nV;

    const int kmax = (bi + 1) * 128;

    float acc[4][4][4];
#pragma unroll
    for (int i = 0; i < 4; i++)
#pragma unroll
        for (int j = 0; j < 4; j++)
#pragma unroll
            for (int r = 0; r < 4; r++) acc[i][j][r] = 0.f;

    float4 xa0, xa1, ya0, ya1;
    float vv[2][8];

    // prefetch chunk 0
    xa0 = *(const float4*)(a1p);  xa1 = *(const float4*)(a1p + 4);
    ya0 = *(const float4*)(a2p);  ya1 = *(const float4*)(a2p + 4);
#pragma unroll
    for (int j = 0; j < 2; j++)
#pragma unroll
        for (int c = 0; c < 8; c++)
            vv[j][c] = vp[(size_t)((kbV0 + j) * 8 + c) * QKV3];

    for (int k0 = 0; k0 < kmax; k0 += 32) {
        __syncthreads();
        As4[kbA][pA][0] = make_float4(to_tf32(xa0.x), to_tf32(ya0.x), to_tf32(xa1.x), to_tf32(ya1.x));
        As4[kbA][pA][1] = make_float4(to_tf32(xa0.y), to_tf32(ya0.y), to_tf32(xa1.y), to_tf32(ya1.y));
        As4[kbA][pA][2] = make_float4(to_tf32(xa0.z), to_tf32(ya0.z), to_tf32(xa1.z), to_tf32(ya1.z));
        As4[kbA][pA][3] = make_float4(to_tf32(xa0.w), to_tf32(ya0.w), to_tf32(xa1.w), to_tf32(ya1.w));
#pragma unroll
        for (int j = 0; j < 2; j++) {
            int kb = kbV0 + j;
            Bs2[kb][nV][0] = make_float2(to_tf32(vv[j][0]), to_tf32(vv[j][4]));
            Bs2[kb][nV][1] = make_float2(to_tf32(vv[j][1]), to_tf32(vv[j][5]));
            Bs2[kb][nV][2] = make_float2(to_tf32(vv[j][2]), to_tf32(vv[j][6]));
            Bs2[kb][nV][3] = make_float2(to_tf32(vv[j][3]), to_tf32(vv[j][7]));
        }
        __syncthreads();

        int kn = k0 + 32;
        if (kn < kmax) {
            xa0 = *(const float4*)(a1p + kn);  xa1 = *(const float4*)(a1p + kn + 4);
            ya0 = *(const float4*)(a2p + kn);  ya1 = *(const float4*)(a2p + kn + 4);
#pragma unroll
            for (int j = 0; j < 2; j++)
#pragma unroll
                for (int c = 0; c < 8; c++)
                    vv[j][c] = vp[(size_t)(kn + (kbV0 + j) * 8 + c) * QKV3];
        }

#pragma unroll
        for (int kb = 0; kb < 4; kb++) {
            float4 af[4]; float2 bf[4];
#pragma unroll
            for (int mt = 0; mt < 4; mt++)
                af[mt] = As4[kb][((warp_m * 4 + mt) << 3) + t4][c4];
#pragma unroll
            for (int nt = 0; nt < 4; nt++)
                bf[nt] = Bs2[kb][warp_n * 32 + nt * 8 + t4][c4];
#pragma unroll
            for (int mt = 0; mt < 4; mt++)
#pragma unroll
                for (int nt = 0; nt < 4; nt++) mma8(acc[mt][nt], af[mt], bf[nt]);
        }
    }

#pragma unroll
    for (int mt = 0; mt < 4; mt++) {
        int r0 = bi * 128 + warp_m * 64 + mt * 16 + t4;
#pragma unroll
        for (int nt = 0; nt < 4; nt++) {
            int cc = h * HD + warp_n * 32 + nt * 8 + 2 * c4;
            *(float2*)&ctx[(size_t)r0 * Hdim + cc] =
                make_float2(acc[mt][nt][0], acc[mt][nt][1]);
            *(float2*)&ctx[(size_t)(r0 + 8) * Hdim + cc] =
                make_float2(acc[mt][nt][2], acc[mt][nt][3]);
        }
    }
}

// ---------------------------------------------------------------------------
// Launch
// ---------------------------------------------------------------------------
extern "C" void kernel_launch(void* const* d_in, const int* in_sizes, int n_in,
                              void* d_out, int out_size)
{
    const float* hidden  = (const float*)d_in[0];
    // d_in[1] = attention_mask (causal; structure known, unused)
    const float* W_qkv   = (const float*)d_in[2];
    const float* b_qkv   = (const float*)d_in[3];
    const float* W_dense = (const float*)d_in[4];
    const float* b_dense = (const float*)d_in[5];
    float* out = (float*)d_out;

    float *qkv, *scores, *ctx;
    cudaGetSymbolAddress((void**)&qkv,    g_qkv);
    cudaGetSymbolAddress((void**)&scores, g_scores);
    cudaGetSymbolAddress((void**)&ctx,    g_ctx);

    // 1) QKV GEMM: [2048,4096] x [12288,4096]^T -> [2048,12288]
    {
        dim3 grid(QKV3 / 128, S / 128);
        gemm_tc_nt<<<grid, 256>>>(hidden, W_qkv, b_qkv, qkv,
                                  Hdim, Hdim, Hdim, QKV3);
    }

    // 2) RoPE in place on q,k
    {
        int total = S * NH * 16 * 2;
        rope_kernel<<<(total + 255) / 256, 256>>>(qkv);
    }

    // 3) Scores with causal mask + scale
    {
        dim3 grid(S / 128, S / 128, NH);
        scores_tc<<<grid, 256>>>(qkv, scores);
    }

    // 4) Row softmax
    {
        dim3 grid(S, NH);
        softmax_kernel<<<grid, 256>>>(scores);
    }

    // 5) P @ V -> ctx [2048, 4096]
    {
        dim3 grid(S / 128, NH);
        pv_tc<<<grid, 256>>>(scores, qkv, ctx);
    }

    // 6) Dense GEMM: ctx [2048,4096] x W_dense^T -> out
    {
        dim3 grid(Hdim / 128, S / 128);
        gemm_tc_nt<<<grid, 256>>>(ctx, W_dense, b_dense, out,
                                  Hdim, Hdim, Hdim, Hdim);
    }
}

// round 5
// speedup vs baseline: 2.9901x; 1.0613x over previous
#include <cuda_runtime.h>
#include <math.h>

// Problem constants
#define S    2048
#define Hdim 4096
#define NH   32
#define HD   128
#define QKV3 12288            // 3*Hdim
#define HSTRIDE 384           // 3*HD per head inside a qkv row

// Scratch (device globals; no runtime allocation)
__device__ float g_qkv[(size_t)S * QKV3];            // 100 MB
__device__ float g_ctx[(size_t)S * Hdim];            // 33 MB

// ---------------------------------------------------------------------------
// tf32 helpers
// ---------------------------------------------------------------------------
__device__ __forceinline__ float to_tf32(float x) {
    unsigned r;
    asm("cvt.rna.tf32.f32 %0, %1;" : "=r"(r) : "f"(x));
    return __uint_as_float(r);
}

__device__ __forceinline__ void mma8(float c[4], const float4& a, const float2& b) {
    asm volatile(
        "mma.sync.aligned.m16n8k8.row.col.f32.tf32.tf32.f32 "
        "{%0,%1,%2,%3},{%4,%5,%6,%7},{%8,%9},{%0,%1,%2,%3};\n"
        : "+f"(c[0]), "+f"(c[1]), "+f"(c[2]), "+f"(c[3])
        : "r"(__float_as_uint(a.x)), "r"(__float_as_uint(a.y)),
          "r"(__float_as_uint(a.z)), "r"(__float_as_uint(a.w)),
          "r"(__float_as_uint(b.x)), "r"(__float_as_uint(b.y)));
}

// Shared-tile layouts (128x128 block tile, BK=32):
//  As4[kb][p][c] : float4 = (A[m1][k], A[m1+8][k], A[m1][k+4], A[m1+8][k+4])
//                  k = kb*8+c, p = g*8+r8, m1 = g*16+r8
//  Bs2[kb][n][c] : float2 = (B[n][k], B[n][k+4]), k = kb*8+c

// ---------------------------------------------------------------------------
// Generic NT GEMM: C[m,n] = sum_k A[m,k]*B[n,k] + bias[n]
// ---------------------------------------------------------------------------
__global__ __launch_bounds__(256) void gemm_tc_nt(
    const float* __restrict__ A, const float* __restrict__ B,
    const float* __restrict__ bias, float* __restrict__ C,
    int K, int lda, int ldb, int ldc)
{
    __shared__ float4 As4[4][64][4];   // 16 KB
    __shared__ float2 Bs2[4][128][4];  // 16 KB

    const int tid = threadIdx.x, lane = tid & 31, wid = tid >> 5;
    const int warp_m = wid & 1, warp_n = wid >> 1;   // 2 x 4 warps
    const int t4 = lane >> 2, c4 = lane & 3;

    const int kbA = tid & 3, pA = tid >> 2;          // 4 x 64
    const int m1  = ((pA >> 3) << 4) + (pA & 7);
    const int kbB = tid & 3, nB = tid >> 2;

    const float* a1p = A + (size_t)(blockIdx.y * 128 + m1) * lda + kbA * 8;
    const float* a2p = a1p + (size_t)8 * lda;
    const float* b1p = B + (size_t)(blockIdx.x * 128 + nB) * ldb + kbB * 8;
    const float* b2p = b1p + (size_t)64 * ldb;

    float acc[4][4][4];
#pragma unroll
    for (int i = 0; i < 4; i++)
#pragma unroll
        for (int j = 0; j < 4; j++)
#pragma unroll
            for (int r = 0; r < 4; r++) acc[i][j][r] = 0.f;

    float4 xa0, xa1, ya0, ya1, u0, u1, v0, v1;
    xa0 = *(const float4*)(a1p);     xa1 = *(const float4*)(a1p + 4);
    ya0 = *(const float4*)(a2p);     ya1 = *(const float4*)(a2p + 4);
    u0  = *(const float4*)(b1p);     u1  = *(const float4*)(b1p + 4);
    v0  = *(const float4*)(b2p);     v1  = *(const float4*)(b2p + 4);

    for (int k0 = 0; k0 < K; k0 += 32) {
        __syncthreads();
        As4[kbA][pA][0] = make_float4(to_tf32(xa0.x), to_tf32(ya0.x), to_tf32(xa1.x), to_tf32(ya1.x));
        As4[kbA][pA][1] = make_float4(to_tf32(xa0.y), to_tf32(ya0.y), to_tf32(xa1.y), to_tf32(ya1.y));
        As4[kbA][pA][2] = make_float4(to_tf32(xa0.z), to_tf32(ya0.z), to_tf32(xa1.z), to_tf32(ya1.z));
        As4[kbA][pA][3] = make_float4(to_tf32(xa0.w), to_tf32(ya0.w), to_tf32(xa1.w), to_tf32(ya1.w));
        Bs2[kbB][nB][0]      = make_float2(to_tf32(u0.x), to_tf32(u1.x));
        Bs2[kbB][nB][1]      = make_float2(to_tf32(u0.y), to_tf32(u1.y));
        Bs2[kbB][nB][2]      = make_float2(to_tf32(u0.z), to_tf32(u1.z));
        Bs2[kbB][nB][3]      = make_float2(to_tf32(u0.w), to_tf32(u1.w));
        Bs2[kbB][nB + 64][0] = make_float2(to_tf32(v0.x), to_tf32(v1.x));
        Bs2[kbB][nB + 64][1] = make_float2(to_tf32(v0.y), to_tf32(v1.y));
        Bs2[kbB][nB + 64][2] = make_float2(to_tf32(v0.z), to_tf32(v1.z));
        Bs2[kbB][nB + 64][3] = make_float2(to_tf32(v0.w), to_tf32(v1.w));
        __syncthreads();

        int kn = k0 + 32;
        if (kn < K) {
            xa0 = *(const float4*)(a1p + kn);     xa1 = *(const float4*)(a1p + kn + 4);
            ya0 = *(const float4*)(a2p + kn);     ya1 = *(const float4*)(a2p + kn + 4);
            u0  = *(const float4*)(b1p + kn);     u1  = *(const float4*)(b1p + kn + 4);
            v0  = *(const float4*)(b2p + kn);     v1  = *(const float4*)(b2p + kn + 4);
        }

#pragma unroll
        for (int kb = 0; kb < 4; kb++) {
            float4 af[4]; float2 bf[4];
#pragma unroll
            for (int mt = 0; mt < 4; mt++)
                af[mt] = As4[kb][((warp_m * 4 + mt) << 3) + t4][c4];
#pragma unroll
            for (int nt = 0; nt < 4; nt++)
                bf[nt] = Bs2[kb][warp_n * 32 + nt * 8 + t4][c4];
#pragma unroll
            for (int mt = 0; mt < 4; mt++)
#pragma unroll
                for (int nt = 0; nt < 4; nt++) mma8(acc[mt][nt], af[mt], bf[nt]);
        }
    }

#pragma unroll
    for (int mt = 0; mt < 4; mt++) {
        int r0 = blockIdx.y * 128 + warp_m * 64 + mt * 16 + t4;
#pragma unroll
        for (int nt = 0; nt < 4; nt++) {
            int cc = blockIdx.x * 128 + warp_n * 32 + nt * 8 + 2 * c4;
            float b0 = bias[cc], b1 = bias[cc + 1];
            *(float2*)&C[(size_t)r0 * ldc + cc] =
                make_float2(acc[mt][nt][0] + b0, acc[mt][nt][1] + b1);
            *(float2*)&C[(size_t)(r0 + 8) * ldc + cc] =
                make_float2(acc[mt][nt][2] + b0, acc[mt][nt][3] + b1);
        }
    }
}

// ---------------------------------------------------------------------------
// RoPE (in place on q,k slices of g_qkv)
// ---------------------------------------------------------------------------
__global__ void rope_kernel(float* __restrict__ qkv)
{
    int idx = blockIdx.x * blockDim.x + threadIdx.x;
    const int total = S * NH * 16 * 2;
    if (idx >= total) return;

    int i = idx & 15;
    int r = idx >> 4;
    int h = r & 31;
    r >>= 5;
    int which = r & 1;
    int s = r >> 1;

    float inv = powf(10000.0f, -(float)i / 16.0f);
    float ang = (float)s * inv;
    float c, sn;
    sincosf(ang, &sn, &c);

    float* base = qkv + (size_t)s * QKV3 + h * HSTRIDE + which * HD;
    float x1 = base[i];
    float x2 = base[i + 16];
    base[i]      = x1 * c - x2 * sn;
    base[i + 16] = x2 * c + x1 * sn;
}

// ---------------------------------------------------------------------------
// Fused flash attention: per block = one (head, 128-row Q tile).
// Streams K/V tiles (causal), online softmax, O accumulated in registers.
// ---------------------------------------------------------------------------
__global__ __launch_bounds__(256) void flash_kernel(
    const float* __restrict__ qkv, float* __restrict__ ctx)
{
    const int bi = (int)(gridDim.x - 1 - blockIdx.x);   // heavy tiles first
    const int h  = blockIdx.y;

    __shared__ float4 As4[4][64][4];    // 16 KB (Q chunk / P chunk)
    __shared__ float2 Bs2[4][128][4];   // 16 KB (K chunk / V chunk)
    __shared__ float  red[128][4];      //  2 KB (rowmax / rowsum partials)

    const int tid = threadIdx.x, lane = tid & 31, wid = tid >> 5;
    const int warp_m = wid & 1, warp_n = wid >> 1;
    const int t4 = lane >> 2, c4 = lane & 3;

    const int kbA = tid & 3, pA = tid >> 2;
    const int m1  = ((pA >> 3) << 4) + (pA & 7);
    const int kbB = tid & 3, nB = tid >> 2;
    const int nV  = tid & 127;           // V column (d)
    const int kbV0 = (tid >> 7) * 2;     // covers kb = kbV0, kbV0+1

    // Q pointers (fixed across tiles)
    const float* a1p = qkv + (size_t)(bi * 128 + m1) * QKV3 + h * HSTRIDE + kbA * 8;
    const float* a2p = a1p + (size_t)8 * QKV3;
    const float* Vcol = qkv + h * HSTRIDE + 2 * HD + nV;

    // P-fragment write geometry (thread holds cols of its warp_n chunk)
    const int c_base = (c4 & 1) * 2;
    const int c_hi   = (c4 >> 1) * 2;    // 0 -> .xy, 2 -> .zw

    float o_acc[4][4][4];
    float m_run[4][2], l_run[4][2];
#pragma unroll
    for (int i = 0; i < 4; i++) {
        m_run[i][0] = -1e30f; m_run[i][1] = -1e30f;
        l_run[i][0] = 0.f;    l_run[i][1] = 0.f;
#pragma unroll
        for (int j = 0; j < 4; j++)
#pragma unroll
            for (int r = 0; r < 4; r++) o_acc[i][j][r] = 0.f;
    }

    const float scale = 0.08838834764831845f;   // 1/sqrt(128)

    for (int bj = 0; bj <= bi; bj++) {
        // ================= Q @ K^T =================
        float sc[4][4][4];
#pragma unroll
        for (int i = 0; i < 4; i++)
#pragma unroll
            for (int j = 0; j < 4; j++)
#pragma unroll
                for (int r = 0; r < 4; r++) sc[i][j][r] = 0.f;

        const float* b1p = qkv + (size_t)(bj * 128 + nB) * QKV3 + h * HSTRIDE + HD + kbB * 8;
        const float* b2p = b1p + (size_t)64 * QKV3;

        float4 xa0, xa1, ya0, ya1, u0, u1, v0, v1;
        xa0 = *(const float4*)(a1p);  xa1 = *(const float4*)(a1p + 4);
        ya0 = *(const float4*)(a2p);  ya1 = *(const float4*)(a2p + 4);
        u0  = *(const float4*)(b1p);  u1  = *(const float4*)(b1p + 4);
        v0  = *(const float4*)(b2p);  v1  = *(const float4*)(b2p + 4);

        for (int k0 = 0; k0 < HD; k0 += 32) {
            __syncthreads();   // smem buffers free (prev phase done)
            As4[kbA][pA][0] = make_float4(to_tf32(xa0.x), to_tf32(ya0.x), to_tf32(xa1.x), to_tf32(ya1.x));
            As4[kbA][pA][1] = make_float4(to_tf32(xa0.y), to_tf32(ya0.y), to_tf32(xa1.y), to_tf32(ya1.y));
            As4[kbA][pA][2] = make_float4(to_tf32(xa0.z), to_tf32(ya0.z), to_tf32(xa1.z), to_tf32(ya1.z));
            As4[kbA][pA][3] = make_float4(to_tf32(xa0.w), to_tf32(ya0.w), to_tf32(xa1.w), to_tf32(ya1.w));
            Bs2[kbB][nB][0]      = make_float2(to_tf32(u0.x), to_tf32(u1.x));
            Bs2[kbB][nB][1]      = make_float2(to_tf32(u0.y), to_tf32(u1.y));
            Bs2[kbB][nB][2]      = make_float2(to_tf32(u0.z), to_tf32(u1.z));
            Bs2[kbB][nB][3]      = make_float2(to_tf32(u0.w), to_tf32(u1.w));
            Bs2[kbB][nB + 64][0] = make_float2(to_tf32(v0.x), to_tf32(v1.x));
            Bs2[kbB][nB + 64][1] = make_float2(to_tf32(v0.y), to_tf32(v1.y));
            Bs2[kbB][nB + 64][2] = make_float2(to_tf32(v0.z), to_tf32(v1.z));
            Bs2[kbB][nB + 64][3] = make_float2(to_tf32(v0.w), to_tf32(v1.w));
            __syncthreads();

            int kn = k0 + 32;
            if (kn < HD) {
                xa0 = *(const float4*)(a1p + kn);  xa1 = *(const float4*)(a1p + kn + 4);
                ya0 = *(const float4*)(a2p + kn);  ya1 = *(const float4*)(a2p + kn + 4);
                u0  = *(const float4*)(b1p + kn);  u1  = *(const float4*)(b1p + kn + 4);
                v0  = *(const float4*)(b2p + kn);  v1  = *(const float4*)(b2p + kn + 4);
            }

#pragma unroll
            for (int kb = 0; kb < 4; kb++) {
                float4 af[4]; float2 bf[4];
#pragma unroll
                for (int mt = 0; mt < 4; mt++)
                    af[mt] = As4[kb][((warp_m * 4 + mt) << 3) + t4][c4];
#pragma unroll
                for (int nt = 0; nt < 4; nt++)
                    bf[nt] = Bs2[kb][warp_n * 32 + nt * 8 + t4][c4];
#pragma unroll
                for (int mt = 0; mt < 4; mt++)
#pragma unroll
                    for (int nt = 0; nt < 4; nt++) mma8(sc[mt][nt], af[mt], bf[nt]);
            }
        }

        // ============ scale + causal mask ============
        if (bj == bi) {
#pragma unroll
            for (int mt = 0; mt < 4; mt++) {
                int r0 = warp_m * 64 + mt * 16 + t4;
#pragma unroll
                for (int nt = 0; nt < 4; nt++) {
                    int cc = warp_n * 32 + nt * 8 + 2 * c4;
                    sc[mt][nt][0] = (cc     <= r0    ) ? sc[mt][nt][0] * scale : -1e30f;
                    sc[mt][nt][1] = (cc + 1 <= r0    ) ? sc[mt][nt][1] * scale : -1e30f;
                    sc[mt][nt][2] = (cc     <= r0 + 8) ? sc[mt][nt][2] * scale : -1e30f;
                    sc[mt][nt][3] = (cc + 1 <= r0 + 8) ? sc[mt][nt][3] * scale : -1e30f;
                }
            }
        } else {
#pragma unroll
            for (int mt = 0; mt < 4; mt++)
#pragma unroll
                for (int nt = 0; nt < 4; nt++)
#pragma unroll
                    for (int r = 0; r < 4; r++) sc[mt][nt][r] *= scale;
        }

        // ============ online softmax ============
        // 1) per-warp row max over this warp's 32 cols
        float pmax[4][2];
#pragma unroll
        for (int mt = 0; mt < 4; mt++) {
            float p0 = -1e30f, p1 = -1e30f;
#pragma unroll
            for (int nt = 0; nt < 4; nt++) {
                p0 = fmaxf(p0, fmaxf(sc[mt][nt][0], sc[mt][nt][1]));
                p1 = fmaxf(p1, fmaxf(sc[mt][nt][2], sc[mt][nt][3]));
            }
#pragma unroll
            for (int off = 1; off <= 2; off <<= 1) {
                p0 = fmaxf(p0, __shfl_xor_sync(0xffffffffu, p0, off));
                p1 = fmaxf(p1, __shfl_xor_sync(0xffffffffu, p1, off));
            }
            pmax[mt][0] = p0; pmax[mt][1] = p1;
        }
        if (c4 == 0) {
#pragma unroll
            for (int mt = 0; mt < 4; mt++) {
                red[warp_m * 64 + mt * 16 + t4][warp_n]     = pmax[mt][0];
                red[warp_m * 64 + mt * 16 + t4 + 8][warp_n] = pmax[mt][1];
            }
        }
        __syncthreads();

        float m_new[4][2], alpha[4][2];
#pragma unroll
        for (int mt = 0; mt < 4; mt++) {
#pragma unroll
            for (int hf = 0; hf < 2; hf++) {
                int r = warp_m * 64 + mt * 16 + t4 + hf * 8;
                float M = fmaxf(fmaxf(red[r][0], red[r][1]),
                                fmaxf(red[r][2], red[r][3]));
                float mn = fmaxf(m_run[mt][hf], M);
                alpha[mt][hf] = __expf(m_run[mt][hf] - mn);
                m_new[mt][hf] = mn;
            }
        }
        __syncthreads();   // all reads of red done before reuse

        // 2) exp + per-warp row sum
        float psum[4][2];
#pragma unroll
        for (int mt = 0; mt < 4; mt++) {
            float s0 = 0.f, s1 = 0.f;
#pragma unroll
            for (int nt = 0; nt < 4; nt++) {
                sc[mt][nt][0] = __expf(sc[mt][nt][0] - m_new[mt][0]);
                sc[mt][nt][1] = __expf(sc[mt][nt][1] - m_new[mt][0]);
                sc[mt][nt][2] = __expf(sc[mt][nt][2] - m_new[mt][1]);
                sc[mt][nt][3] = __expf(sc[mt][nt][3] - m_new[mt][1]);
                s0 += sc[mt][nt][0] + sc[mt][nt][1];
                s1 += sc[mt][nt][2] + sc[mt][nt][3];
            }
#pragma unroll
            for (int off = 1; off <= 2; off <<= 1) {
                s0 += __shfl_xor_sync(0xffffffffu, s0, off);
                s1 += __shfl_xor_sync(0xffffffffu, s1, off);
            }
            psum[mt][0] = s0; psum[mt][1] = s1;
        }
        if (c4 == 0) {
#pragma unroll
            for (int mt = 0; mt < 4; mt++) {
                red[warp_m * 64 + mt * 16 + t4][warp_n]     = psum[mt][0];
                red[warp_m * 64 + mt * 16 + t4 + 8][warp_n] = psum[mt][1];
            }
        }
        __syncthreads();

#pragma unroll
        for (int mt = 0; mt < 4; mt++) {
#pragma unroll
            for (int hf = 0; hf < 2; hf++) {
                int r = warp_m * 64 + mt * 16 + t4 + hf * 8;
                float ts = red[r][0] + red[r][1] + red[r][2] + red[r][3];
                l_run[mt][hf] = l_run[mt][hf] * alpha[mt][hf] + ts;
                m_run[mt][hf] = m_new[mt][hf];
            }
            float a0 = alpha[mt][0], a1 = alpha[mt][1];
#pragma unroll
            for (int nt = 0; nt < 4; nt++) {
                o_acc[mt][nt][0] *= a0;  o_acc[mt][nt][1] *= a0;
                o_acc[mt][nt][2] *= a1;  o_acc[mt][nt][3] *= a1;
            }
        }

        // ============ P @ V (4 chunks of 32 keys) ============
        float vv[2][8];
        {
            const float* vp = Vcol + (size_t)(bj * 128) * QKV3;
#pragma unroll
            for (int j = 0; j < 2; j++)
#pragma unroll
                for (int c = 0; c < 8; c++)
                    vv[j][c] = vp[(size_t)((kbV0 + j) * 8 + c) * QKV3];
        }

        for (int kc = 0; kc < 4; kc++) {
            __syncthreads();   // prev mma done; smem free
            // P chunk: owned by warps with warp_n == kc
            if (warp_n == kc) {
#pragma unroll
                for (int mt = 0; mt < 4; mt++) {
                    int p = ((warp_m * 4 + mt) << 3) + t4;
#pragma unroll
                    for (int nt = 0; nt < 4; nt++) {
                        float* s0 = ((float*)&As4[nt][p][c_base]) + c_hi;
                        s0[0] = to_tf32(sc[mt][nt][0]);
                        s0[1] = to_tf32(sc[mt][nt][2]);
                        float* s1 = ((float*)&As4[nt][p][c_base + 1]) + c_hi;
                        s1[0] = to_tf32(sc[mt][nt][1]);
                        s1[1] = to_tf32(sc[mt][nt][3]);
                    }
                }
            }
            // V chunk -> Bs2
#pragma unroll
            for (int j = 0; j < 2; j++) {
                int kb = kbV0 + j;
                Bs2[kb][nV][0] = make_float2(to_tf32(vv[j][0]), to_tf32(vv[j][4]));
                Bs2[kb][nV][1] = make_float2(to_tf32(vv[j][1]), to_tf32(vv[j][5]));
                Bs2[kb][nV][2] = make_float2(to_tf32(vv[j][2]), to_tf32(vv[j][6]));
                Bs2[kb][nV][3] = make_float2(to_tf32(vv[j][3]), to_tf32(vv[j][7]));
            }
            __syncthreads();

            // prefetch next V chunk
            if (kc < 3) {
                const float* vp = Vcol + (size_t)(bj * 128 + (kc + 1) * 32) * QKV3;
#pragma unroll
                for (int j = 0; j < 2; j++)
#pragma unroll
                    for (int c = 0; c < 8; c++)
                        vv[j][c] = vp[(size_t)((kbV0 + j) * 8 + c) * QKV3];
            }

#pragma unroll
            for (int kb = 0; kb < 4; kb++) {
                float4 af[4]; float2 bf[4];
#pragma unroll
                for (int mt = 0; mt < 4; mt++)
                    af[mt] = As4[kb][((warp_m * 4 + mt) << 3) + t4][c4];
#pragma unroll
                for (int nt = 0; nt < 4; nt++)
                    bf[nt] = Bs2[kb][warp_n * 32 + nt * 8 + t4][c4];
#pragma unroll
                for (int mt = 0; mt < 4; mt++)
#pragma unroll
                    for (int nt = 0; nt < 4; nt++) mma8(o_acc[mt][nt], af[mt], bf[nt]);
            }
        }
    }

    // ============ epilogue: normalize + store ============
#pragma unroll
    for (int mt = 0; mt < 4; mt++) {
        int r0 = bi * 128 + warp_m * 64 + mt * 16 + t4;
        float inv0 = 1.0f / l_run[mt][0];
        float inv1 = 1.0f / l_run[mt][1];
#pragma unroll
        for (int nt = 0; nt < 4; nt++) {
            int cc = h * HD + warp_n * 32 + nt * 8 + 2 * c4;
            *(float2*)&ctx[(size_t)r0 * Hdim + cc] =
                make_float2(o_acc[mt][nt][0] * inv0, o_acc[mt][nt][1] * inv0);
            *(float2*)&ctx[(size_t)(r0 + 8) * Hdim + cc] =
                make_float2(o_acc[mt][nt][2] * inv1, o_acc[mt][nt][3] * inv1);
        }
    }
}

// ---------------------------------------------------------------------------
// Launch
// ---------------------------------------------------------------------------
extern "C" void kernel_launch(void* const* d_in, const int* in_sizes, int n_in,
                              void* d_out, int out_size)
{
    const float* hidden  = (const float*)d_in[0];
    // d_in[1] = attention_mask (causal; structure known, unused)
    const float* W_qkv   = (const float*)d_in[2];
    const float* b_qkv   = (const float*)d_in[3];
    const float* W_dense = (const float*)d_in[4];
    const float* b_dense = (const float*)d_in[5];
    float* out = (float*)d_out;

    float *qkv, *ctx;
    cudaGetSymbolAddress((void**)&qkv, g_qkv);
    cudaGetSymbolAddress((void**)&ctx, g_ctx);

    // 1) QKV GEMM: [2048,4096] x [12288,4096]^T -> [2048,12288]
    {
        dim3 grid(QKV3 / 128, S / 128);
        gemm_tc_nt<<<grid, 256>>>(hidden, W_qkv, b_qkv, qkv,
                                  Hdim, Hdim, Hdim, QKV3);
    }

    // 2) RoPE in place on q,k
    {
        int total = S * NH * 16 * 2;
        rope_kernel<<<(total + 255) / 256, 256>>>(qkv);
    }

    // 3-5) Fused flash attention -> ctx [2048, 4096]
    {
        dim3 grid(S / 128, NH);
        flash_kernel<<<grid, 256>>>(qkv, ctx);
    }

    // 6) Dense GEMM: ctx [2048,4096] x W_dense^T -> out
    {
        dim3 grid(Hdim / 128, S / 128);
        gemm_tc_nt<<<grid, 256>>>(ctx, W_dense, b_dense, out,
                                  Hdim, Hdim, Hdim, Hdim);
    }
}